// round 1
// baseline (speedup 1.0000x reference)
#include <cuda_runtime.h>
#include <math.h>

#define BB   2
#define SEQL 2048
#define DIM  1024
#define NH   16
#define HD   64
#define HID  2816
#define BS   (BB*SEQL)   // 4096

// ---------------- scratch (static device memory; no allocation allowed) ----
__device__ float sc_mod[(size_t)BS*DIM];
__device__ float sc_q  [(size_t)BS*DIM];
__device__ float sc_k  [(size_t)BS*DIM];
__device__ float sc_v  [(size_t)BS*DIM];
__device__ float sc_ao [(size_t)BS*DIM];
__device__ float sc_x2 [(size_t)BS*DIM];
__device__ float sc_b1 [(size_t)BS*HID];
__device__ float sc_b2 [(size_t)BS*HID];
__device__ float sc_t  [BB*512];
__device__ float sc_cv [BB*2*256];

// ---------------- time projection: t = silu(ada) @ proj_w + proj_b --------
__global__ void k_timeproj(const float* __restrict__ ada, const float* __restrict__ pw,
                           const float* __restrict__ pb, float* __restrict__ t) {
    __shared__ float sa[DIM];
    int b = blockIdx.x;
    int j = threadIdx.x;              // 512 threads
    for (int i = j; i < DIM; i += 512) {
        float v = ada[b*DIM + i];
        sa[i] = v / (1.0f + expf(-v));
    }
    __syncthreads();
    float acc = pb[j];
    #pragma unroll 8
    for (int k = 0; k < DIM; k++) acc += sa[k] * pw[k*512 + j];
    t[b*512 + j] = acc;
}

// ------ build circular-conv kernel: g[n] = (1/256) sum_k f[k] cos(2pi k n/256)
__global__ void k_makeconv(const float* __restrict__ t, float* __restrict__ cv) {
    int slot = blockIdx.x;            // b*2 + which
    int b = slot >> 1, w = slot & 1;
    int n = threadIdx.x;              // 256
    const float* f = t + b*512 + w*256;
    float acc = 0.0f;
    #pragma unroll 4
    for (int k = 0; k < 256; k++) {
        int kn = (k * n) & 255;
        acc += f[k] * cospif(kn * (2.0f / 256.0f));
    }
    cv[slot*256 + n] = acc * (1.0f / 256.0f);
}

// ------ adafm_modulate == per-16x16-patch circular conv (len 256) ----------
__global__ __launch_bounds__(256) void k_modulate(const float* __restrict__ x,
                                                  const float* __restrict__ cv, int which,
                                                  float* __restrict__ out) {
    int b = blockIdx.y;
    int patch = blockIdx.x;           // 0..8191
    int ir = patch >> 6, ic = patch & 63;
    int m = threadIdx.x;              // 0..255
    __shared__ float xp[256], gs[256];
    gs[m] = cv[(b*2 + which)*256 + m];
    int pr = m >> 4, pc = m & 15;
    size_t gi = ((size_t)b*SEQL + ir*16 + pr)*DIM + ic*16 + pc;
    xp[m] = x[gi];
    __syncthreads();
    float acc = 0.0f;
    #pragma unroll 8
    for (int mp = 0; mp < 256; mp++)
        acc += xp[mp] * gs[(m - mp) & 255];
    out[gi] = acc;
}

// ---------------- SGEMM: C[M,N] = A[M,K] @ B[K,N], all row-major -----------
__global__ __launch_bounds__(256) void k_gemm(const float* __restrict__ A,
                                              const float* __restrict__ B,
                                              float* __restrict__ C,
                                              int M, int N, int K) {
    __shared__ float As[16][132];
    __shared__ float Bs[16][132];
    int tid = threadIdx.x;
    int m0 = blockIdx.y * 128, n0 = blockIdx.x * 128;
    int tx = tid & 15, ty = tid >> 4;
    int arow = tid >> 2, acol = (tid & 3) * 4;
    int brow = tid >> 5, bcol = (tid & 31) * 4;
    float c[8][8];
    #pragma unroll
    for (int i = 0; i < 8; i++)
        #pragma unroll
        for (int j = 0; j < 8; j++) c[i][j] = 0.0f;

    for (int k0 = 0; k0 < K; k0 += 16) {
        float4 a0 = *(const float4*)&A[(size_t)(m0 + arow     )*K + k0 + acol];
        float4 a1 = *(const float4*)&A[(size_t)(m0 + arow + 64)*K + k0 + acol];
        As[acol+0][arow] = a0.x; As[acol+1][arow] = a0.y;
        As[acol+2][arow] = a0.z; As[acol+3][arow] = a0.w;
        As[acol+0][arow+64] = a1.x; As[acol+1][arow+64] = a1.y;
        As[acol+2][arow+64] = a1.z; As[acol+3][arow+64] = a1.w;
        float4 b0 = *(const float4*)&B[(size_t)(k0 + brow    )*N + n0 + bcol];
        float4 b1 = *(const float4*)&B[(size_t)(k0 + brow + 8)*N + n0 + bcol];
        *(float4*)&Bs[brow    ][bcol] = b0;
        *(float4*)&Bs[brow + 8][bcol] = b1;
        __syncthreads();
        #pragma unroll
        for (int kk = 0; kk < 16; kk++) {
            float a[8], bb[8];
            *(float4*)(a)     = *(float4*)&As[kk][ty*8];
            *(float4*)(a + 4) = *(float4*)&As[kk][ty*8 + 4];
            *(float4*)(bb)    = *(float4*)&Bs[kk][tx*8];
            *(float4*)(bb + 4)= *(float4*)&Bs[kk][tx*8 + 4];
            #pragma unroll
            for (int i = 0; i < 8; i++)
                #pragma unroll
                for (int j = 0; j < 8; j++) c[i][j] += a[i] * bb[j];
        }
        __syncthreads();
    }
    #pragma unroll
    for (int i = 0; i < 8; i++) {
        float* Cr = &C[(size_t)(m0 + ty*8 + i)*N + n0 + tx*8];
        *(float4*)(Cr)     = make_float4(c[i][0], c[i][1], c[i][2], c[i][3]);
        *(float4*)(Cr + 4) = make_float4(c[i][4], c[i][5], c[i][6], c[i][7]);
    }
}

// ---------------- rotary + justnorm + sqk scale for q,k --------------------
__global__ void k_rope(float* __restrict__ q, float* __restrict__ k,
                       const float* __restrict__ fc, const float* __restrict__ fs,
                       const float* __restrict__ sqk) {
    int r = blockIdx.x*8 + (threadIdx.x >> 5);  // row over B*S*NH
    int lane = threadIdx.x & 31;
    int h = r & (NH - 1);
    int s = (r >> 4) & (SEQL - 1);
    float c  = fc[s*32 + lane];
    float sn = fs[s*32 + lane];
    float2* qp = (float2*)q + (size_t)r*32 + lane;
    float2* kp = (float2*)k + (size_t)r*32 + lane;
    float2 qv = *qp, kv = *kp;
    float qa = qv.x*c - qv.y*sn, qb = qv.x*sn + qv.y*c;
    float ka = kv.x*c - kv.y*sn, kb = kv.x*sn + kv.y*c;
    float sq = qa*qa + qb*qb, sk = ka*ka + kb*kb;
    #pragma unroll
    for (int o = 16; o > 0; o >>= 1) {
        sq += __shfl_xor_sync(0xffffffffu, sq, o);
        sk += __shfl_xor_sync(0xffffffffu, sk, o);
    }
    float iq = 1.0f / fmaxf(sqrtf(sq), 1e-12f);
    float ik = 1.0f / fmaxf(sqrtf(sk), 1e-12f);
    float s0 = sqk[h*HD + 2*lane    ] * 32.0f;   // sqrt(DIM)=32
    float s1 = sqk[h*HD + 2*lane + 1] * 32.0f;
    *qp = make_float2(qa*iq*s0, qb*iq*s1);
    *kp = make_float2(ka*ik*s0, kb*ik*s1);
}

// ---------------- flash-style attention (no mask) --------------------------
#define APAD 68
#define ATTN_SMEM (4*64*APAD*4)
__global__ __launch_bounds__(256) void k_attn(const float* __restrict__ q,
                                              const float* __restrict__ k,
                                              const float* __restrict__ v,
                                              float* __restrict__ o) {
    extern __shared__ float sm[];
    float* Qs = sm;                    // [64][APAD]
    float* Ks = sm + 64*APAD;
    float* Vs = sm + 2*64*APAD;
    float* Ps = sm + 3*64*APAD;
    int qt = blockIdx.x, h = blockIdx.y, b = blockIdx.z;
    int tid = threadIdx.x;
    for (int i = tid; i < 64*64; i += 256) {
        int r = i >> 6, d = i & 63;
        Qs[r*APAD + d] = q[(((size_t)b*SEQL + qt*64 + r)*NH + h)*HD + d];
    }
    int qrow = tid >> 2, seg = tid & 3;
    float mrow = -1e30f, l = 0.0f;
    float oacc[16];
    #pragma unroll
    for (int i = 0; i < 16; i++) oacc[i] = 0.0f;

    for (int kt = 0; kt < SEQL/64; kt++) {
        __syncthreads();
        for (int i = tid; i < 64*64; i += 256) {
            int r = i >> 6, d = i & 63;
            size_t gi = (((size_t)b*SEQL + kt*64 + r)*NH + h)*HD + d;
            Ks[r*APAD + d] = k[gi];
            Vs[r*APAD + d] = v[gi];
        }
        __syncthreads();
        float s[16];
        #pragma unroll
        for (int j = 0; j < 16; j++) s[j] = 0.0f;
        #pragma unroll 4
        for (int d4 = 0; d4 < 64; d4 += 4) {
            float4 qv = *(float4*)&Qs[qrow*APAD + d4];
            #pragma unroll
            for (int j = 0; j < 16; j++) {
                float4 kv = *(float4*)&Ks[(seg + 4*j)*APAD + d4];
                s[j] += qv.x*kv.x + qv.y*kv.y + qv.z*kv.z + qv.w*kv.w;
            }
        }
        float mx = -1e30f;
        #pragma unroll
        for (int j = 0; j < 16; j++) { s[j] *= 8.0f; mx = fmaxf(mx, s[j]); }
        mx = fmaxf(mx, __shfl_xor_sync(0xffffffffu, mx, 1));
        mx = fmaxf(mx, __shfl_xor_sync(0xffffffffu, mx, 2));
        float mnew = fmaxf(mrow, mx);
        float corr = expf(mrow - mnew);
        float ps = 0.0f;
        #pragma unroll
        for (int j = 0; j < 16; j++) { s[j] = expf(s[j] - mnew); ps += s[j]; }
        ps += __shfl_xor_sync(0xffffffffu, ps, 1);
        ps += __shfl_xor_sync(0xffffffffu, ps, 2);
        l = l*corr + ps;
        mrow = mnew;
        #pragma unroll
        for (int i = 0; i < 16; i++) oacc[i] *= corr;
        #pragma unroll
        for (int j = 0; j < 16; j++) Ps[qrow*APAD + seg + 4*j] = s[j];
        __syncwarp();
        #pragma unroll 2
        for (int kk = 0; kk < 64; kk++) {
            float p = Ps[qrow*APAD + kk];
            const float4* vr = (const float4*)&Vs[kk*APAD + seg*16];
            float4 v0 = vr[0], v1 = vr[1], v2 = vr[2], v3 = vr[3];
            oacc[0]  += p*v0.x; oacc[1]  += p*v0.y; oacc[2]  += p*v0.z; oacc[3]  += p*v0.w;
            oacc[4]  += p*v1.x; oacc[5]  += p*v1.y; oacc[6]  += p*v1.z; oacc[7]  += p*v1.w;
            oacc[8]  += p*v2.x; oacc[9]  += p*v2.y; oacc[10] += p*v2.z; oacc[11] += p*v2.w;
            oacc[12] += p*v3.x; oacc[13] += p*v3.y; oacc[14] += p*v3.z; oacc[15] += p*v3.w;
        }
    }
    float inv = 1.0f / l;
    float* op = &o[(((size_t)b*SEQL + qt*64 + qrow)*NH + h)*HD + seg*16];
    #pragma unroll
    for (int i4 = 0; i4 < 4; i4++)
        ((float4*)op)[i4] = make_float4(oacc[i4*4]*inv, oacc[i4*4+1]*inv,
                                        oacc[i4*4+2]*inv, oacc[i4*4+3]*inv);
}

// ---------------- residual: out = norm(norm(x) + lr*(norm(hn)-norm(x))) ----
__device__ __forceinline__ float blockReduceSum256(float v) {
    __shared__ float red[8];
    #pragma unroll
    for (int o = 16; o > 0; o >>= 1) v += __shfl_xor_sync(0xffffffffu, v, o);
    __syncthreads();
    if ((threadIdx.x & 31) == 0) red[threadIdx.x >> 5] = v;
    __syncthreads();
    return red[0]+red[1]+red[2]+red[3]+red[4]+red[5]+red[6]+red[7];
}

__global__ __launch_bounds__(256) void k_residual(const float* __restrict__ x,
                                                  const float* __restrict__ hn,
                                                  const float* __restrict__ alpha,
                                                  float* __restrict__ out) {
    size_t row = blockIdx.x;
    int tid = threadIdx.x;
    const float* xr = x  + row*DIM;
    const float* ar = hn + row*DIM;
    float xs[4], as[4];
    float ssx = 0.0f, ssa = 0.0f;
    #pragma unroll
    for (int i = 0; i < 4; i++) {
        int c = tid + i*256;
        xs[i] = xr[c]; as[i] = ar[c];
        ssx += xs[i]*xs[i]; ssa += as[i]*as[i];
    }
    ssx = blockReduceSum256(ssx);
    ssa = blockReduceSum256(ssa);
    float ix = 1.0f / fmaxf(sqrtf(ssx), 1e-12f);
    float ia = 1.0f / fmaxf(sqrtf(ssa), 1e-12f);
    float y[4]; float ssy = 0.0f;
    #pragma unroll
    for (int i = 0; i < 4; i++) {
        int c = tid + i*256;
        float lr = fabsf(alpha[c] * 1.6f);   // 0.05*sqrt(1024)
        float hh = xs[i]*ix;
        float aa = as[i]*ia;
        y[i] = hh + lr*(aa - hh);
        ssy += y[i]*y[i];
    }
    ssy = blockReduceSum256(ssy);
    float iy = 1.0f / fmaxf(sqrtf(ssy), 1e-12f);
    #pragma unroll
    for (int i = 0; i < 4; i++) out[row*DIM + tid + i*256] = y[i]*iy;
}

// ---------------- GLU: a = silu(a*sv*sqrt(HID)) * (b3*su), in place --------
__global__ void k_glu(float* __restrict__ a, const float* __restrict__ b3,
                      const float* __restrict__ su, const float* __restrict__ sv) {
    int j = blockIdx.x*256 + threadIdx.x;   // column 0..2815
    size_t i = (size_t)blockIdx.y*HID + j;
    float z = a[i] * sv[j] * sqrtf((float)HID);
    float g = z / (1.0f + expf(-z));
    a[i] = g * (b3[i] * su[j]);
}

// ---------------- launch ---------------------------------------------------
extern "C" void kernel_launch(void* const* d_in, const int* in_sizes, int n_in,
                              void* d_out, int out_size) {
    const float* x   = (const float*)d_in[0];
    const float* fc  = (const float*)d_in[1];
    const float* fs  = (const float*)d_in[2];
    const float* ada = (const float*)d_in[3];
    const float* wq  = (const float*)d_in[4];
    const float* wk  = (const float*)d_in[5];
    const float* wv  = (const float*)d_in[6];
    const float* wo  = (const float*)d_in[7];
    const float* sqk = (const float*)d_in[8];
    const float* w1  = (const float*)d_in[9];
    const float* w2  = (const float*)d_in[10];
    const float* w3  = (const float*)d_in[11];
    const float* su  = (const float*)d_in[12];
    const float* sv  = (const float*)d_in[13];
    const float* pw  = (const float*)d_in[14];
    const float* pb  = (const float*)d_in[15];
    const float* aal = (const float*)d_in[16];
    const float* mal = (const float*)d_in[17];
    float* out = (float*)d_out;

    float *p_mod, *p_q, *p_k, *p_v, *p_ao, *p_x2, *p_b1, *p_b2, *p_t, *p_cv;
    cudaGetSymbolAddress((void**)&p_mod, sc_mod);
    cudaGetSymbolAddress((void**)&p_q,   sc_q);
    cudaGetSymbolAddress((void**)&p_k,   sc_k);
    cudaGetSymbolAddress((void**)&p_v,   sc_v);
    cudaGetSymbolAddress((void**)&p_ao,  sc_ao);
    cudaGetSymbolAddress((void**)&p_x2,  sc_x2);
    cudaGetSymbolAddress((void**)&p_b1,  sc_b1);
    cudaGetSymbolAddress((void**)&p_b2,  sc_b2);
    cudaGetSymbolAddress((void**)&p_t,   sc_t);
    cudaGetSymbolAddress((void**)&p_cv,  sc_cv);

    cudaFuncSetAttribute(k_attn, cudaFuncAttributeMaxDynamicSharedMemorySize, ATTN_SMEM);

    // time modulation coefficients -> circular conv kernels
    k_timeproj<<<2, 512>>>(ada, pw, pb, p_t);
    k_makeconv<<<4, 256>>>(p_t, p_cv);

    // ---- attention branch ----
    k_modulate<<<dim3(8192, BB), 256>>>(x, p_cv, 0, p_mod);
    dim3 gQ(DIM/128, BS/128);
    k_gemm<<<gQ, 256>>>(p_mod, wq, p_q, BS, DIM, DIM);
    k_gemm<<<gQ, 256>>>(p_mod, wk, p_k, BS, DIM, DIM);
    k_gemm<<<gQ, 256>>>(p_mod, wv, p_v, BS, DIM, DIM);
    k_rope<<<(BS*NH)/8, 256>>>(p_q, p_k, fc, fs, sqk);
    k_attn<<<dim3(SEQL/64, NH, BB), 256, ATTN_SMEM>>>(p_q, p_k, p_v, p_ao);
    k_gemm<<<gQ, 256>>>(p_ao, wo, p_mod, BS, DIM, DIM);   // h_a into p_mod
    k_residual<<<BS, 256>>>(x, p_mod, aal, p_x2);

    // ---- mlp branch ----
    k_modulate<<<dim3(8192, BB), 256>>>(p_x2, p_cv, 1, p_q);  // reuse p_q
    dim3 gF(HID/128, BS/128);
    k_gemm<<<gF, 256>>>(p_q, w1, p_b1, BS, HID, DIM);
    k_gemm<<<gF, 256>>>(p_q, w3, p_b2, BS, HID, DIM);
    k_glu<<<dim3(HID/256, BS), 256>>>(p_b1, p_b2, su, sv);
    k_gemm<<<dim3(DIM/128, BS/128), 256>>>(p_b1, w2, p_k, BS, DIM, HID);  // h_m into p_k
    k_residual<<<BS, 256>>>(p_x2, p_k, mal, out);
}

// round 2
// speedup vs baseline: 1.2167x; 1.2167x over previous
#include <cuda_runtime.h>
#include <math.h>
#include <stdint.h>

#define BB   2
#define SEQL 2048
#define DIM  1024
#define NH   16
#define HD   64
#define HID  2816
#define BS   (BB*SEQL)   // 4096

// ---------------- scratch (static device memory; no allocation allowed) ----
__device__ float sc_mod[(size_t)BS*DIM];
__device__ float sc_q  [(size_t)BS*DIM];
__device__ float sc_k  [(size_t)BS*DIM];
__device__ float sc_v  [(size_t)BS*DIM];
__device__ float sc_ao [(size_t)BS*DIM];
__device__ float sc_x2 [(size_t)BS*DIM];
__device__ float sc_b1 [(size_t)BS*HID];
__device__ float sc_b2 [(size_t)BS*HID];
__device__ float sc_t  [BB*512];
__device__ float sc_cv [BB*2*256];

// ---------------- time projection: t = silu(ada) @ proj_w + proj_b --------
__global__ void k_timeproj(const float* __restrict__ ada, const float* __restrict__ pw,
                           const float* __restrict__ pb, float* __restrict__ t) {
    __shared__ float sa[DIM];
    int b = blockIdx.x;
    int j = threadIdx.x;              // 512 threads
    for (int i = j; i < DIM; i += 512) {
        float v = ada[b*DIM + i];
        sa[i] = v / (1.0f + expf(-v));
    }
    __syncthreads();
    float acc = pb[j];
    #pragma unroll 8
    for (int k = 0; k < DIM; k++) acc += sa[k] * pw[k*512 + j];
    t[b*512 + j] = acc;
}

// ------ build circular-conv kernel: g[n] = (1/256) sum_k f[k] cos(2pi k n/256)
__global__ void k_makeconv(const float* __restrict__ t, float* __restrict__ cv) {
    int slot = blockIdx.x;            // b*2 + which
    int b = slot >> 1, w = slot & 1;
    int n = threadIdx.x;              // 256
    const float* f = t + b*512 + w*256;
    float acc = 0.0f;
    #pragma unroll 4
    for (int k = 0; k < 256; k++) {
        int kn = (k * n) & 255;
        acc += f[k] * cospif(kn * (2.0f / 256.0f));
    }
    cv[slot*256 + n] = acc * (1.0f / 256.0f);
}

// ------ adafm_modulate == per-16x16-patch circular conv (len 256) ----------
__global__ __launch_bounds__(256) void k_modulate(const float* __restrict__ x,
                                                  const float* __restrict__ cv, int which,
                                                  float* __restrict__ out) {
    int b = blockIdx.y;
    int patch = blockIdx.x;           // 0..8191
    int ir = patch >> 6, ic = patch & 63;
    int m = threadIdx.x;              // 0..255
    __shared__ float xp[256], gs[256];
    gs[m] = cv[(b*2 + which)*256 + m];
    int pr = m >> 4, pc = m & 15;
    size_t gi = ((size_t)b*SEQL + ir*16 + pr)*DIM + ic*16 + pc;
    xp[m] = x[gi];
    __syncthreads();
    float acc = 0.0f;
    #pragma unroll 8
    for (int mp = 0; mp < 256; mp++)
        acc += xp[mp] * gs[(m - mp) & 255];
    out[gi] = acc;
}

// ---------------- tf32 tensor-core GEMM: C[M,N] = A[M,K] @ B[K,N] ----------
// 128x128 tile, K-step 32. 8 warps (2x4): each warp 64x32 via m16n8k8 frags.
// Smem K-major, row stride 136 (8k+m mod 32 -> conflict-free frag loads).
#define GSTR 136
#define GEMM_STAGE (32*GSTR)            // u32 per operand per stage (4352)
#define GEMM_SMEM  (2*2*GEMM_STAGE*4)   // 69632 bytes

__device__ __forceinline__ uint32_t f2tf(float x) {
    uint32_t r; asm("cvt.rna.tf32.f32 %0, %1;" : "=r"(r) : "f"(x)); return r;
}
__device__ __forceinline__ void mma_tf32(float* d, const uint32_t* a, const uint32_t* b) {
    asm volatile("mma.sync.aligned.m16n8k8.row.col.f32.tf32.tf32.f32 "
        "{%0,%1,%2,%3}, {%4,%5,%6,%7}, {%8,%9}, {%0,%1,%2,%3};\n"
        : "+f"(d[0]), "+f"(d[1]), "+f"(d[2]), "+f"(d[3])
        : "r"(a[0]), "r"(a[1]), "r"(a[2]), "r"(a[3]), "r"(b[0]), "r"(b[1]));
}

__global__ __launch_bounds__(256) void k_gemm_tf32(const float* __restrict__ A,
                                                   const float* __restrict__ B,
                                                   float* __restrict__ C,
                                                   int M, int N, int K) {
    extern __shared__ uint32_t smg[];
    const int tid  = threadIdx.x;
    const int lane = tid & 31, wid = tid >> 5;
    const int wm = wid >> 2, wn = wid & 3;         // 2 x 4 warp grid
    const int m0 = blockIdx.y * 128, n0 = blockIdx.x * 128;
    const int lr = lane >> 2, lc = lane & 3;       // groupID, tid-in-group

    float acc[4][4][4];
    #pragma unroll
    for (int i = 0; i < 4; i++)
        #pragma unroll
        for (int j = 0; j < 4; j++)
            #pragma unroll
            for (int r = 0; r < 4; r++) acc[i][j][r] = 0.0f;

    // per-thread global load coords
    const int a_row = tid & 127;                 // one A row per thread
    const int a_kb  = (tid >> 7) * 4;            // 0 or 4
    const float* Arow = A + (size_t)(m0 + a_row) * K;
    // B: per i: kr = wid + 8i, nc = lane*4
    const float* Bcol = B + n0 + lane * 4;

    const int KT = K >> 5;
    int s = 0;

    // ---- preload tile 0 ----
    {
        uint32_t* As = smg;
        uint32_t* Bs = smg + GEMM_STAGE;
        #pragma unroll
        for (int i = 0; i < 4; i++) {
            int kc = a_kb + 8 * i;
            float4 av = *(const float4*)&Arow[kc];
            As[(kc+0)*GSTR + a_row] = f2tf(av.x);
            As[(kc+1)*GSTR + a_row] = f2tf(av.y);
            As[(kc+2)*GSTR + a_row] = f2tf(av.z);
            As[(kc+3)*GSTR + a_row] = f2tf(av.w);
            int kr = wid + 8 * i;
            float4 bv = *(const float4*)&Bcol[(size_t)kr * N];
            uint4 bt = make_uint4(f2tf(bv.x), f2tf(bv.y), f2tf(bv.z), f2tf(bv.w));
            *(uint4*)&Bs[kr*GSTR + lane*4] = bt;
        }
    }
    __syncthreads();

    float4 anx[4], bnx[4];
    for (int kt = 0; kt < KT; kt++) {
        const bool more = (kt + 1 < KT);
        if (more) {
            int k0n = (kt + 1) << 5;
            #pragma unroll
            for (int i = 0; i < 4; i++) {
                anx[i] = *(const float4*)&Arow[k0n + a_kb + 8*i];
                bnx[i] = *(const float4*)&Bcol[(size_t)(k0n + wid + 8*i) * N];
            }
        }
        const uint32_t* As = smg + s * 2 * GEMM_STAGE;
        const uint32_t* Bs = As + GEMM_STAGE;
        #pragma unroll
        for (int ks = 0; ks < 4; ks++) {
            uint32_t af[4][4], bf[4][2];
            const int k = ks * 8 + lc;
            #pragma unroll
            for (int mf = 0; mf < 4; mf++) {
                int m = wm * 64 + mf * 16 + lr;
                af[mf][0] = As[(k    )*GSTR + m];
                af[mf][1] = As[(k    )*GSTR + m + 8];
                af[mf][2] = As[(k + 4)*GSTR + m];
                af[mf][3] = As[(k + 4)*GSTR + m + 8];
            }
            #pragma unroll
            for (int nf = 0; nf < 4; nf++) {
                int n = wn * 32 + nf * 8 + lr;
                bf[nf][0] = Bs[(k    )*GSTR + n];
                bf[nf][1] = Bs[(k + 4)*GSTR + n];
            }
            #pragma unroll
            for (int mf = 0; mf < 4; mf++)
                #pragma unroll
                for (int nf = 0; nf < 4; nf++)
                    mma_tf32(acc[mf][nf], af[mf], bf[nf]);
        }
        if (more) {
            uint32_t* Ad = smg + (s ^ 1) * 2 * GEMM_STAGE;
            uint32_t* Bd = Ad + GEMM_STAGE;
            #pragma unroll
            for (int i = 0; i < 4; i++) {
                int kc = a_kb + 8 * i;
                Ad[(kc+0)*GSTR + a_row] = f2tf(anx[i].x);
                Ad[(kc+1)*GSTR + a_row] = f2tf(anx[i].y);
                Ad[(kc+2)*GSTR + a_row] = f2tf(anx[i].z);
                Ad[(kc+3)*GSTR + a_row] = f2tf(anx[i].w);
                int kr = wid + 8 * i;
                uint4 bt = make_uint4(f2tf(bnx[i].x), f2tf(bnx[i].y),
                                      f2tf(bnx[i].z), f2tf(bnx[i].w));
                *(uint4*)&Bd[kr*GSTR + lane*4] = bt;
            }
            s ^= 1;
            __syncthreads();
        }
    }

    // ---- epilogue ----
    #pragma unroll
    for (int mf = 0; mf < 4; mf++) {
        int mrow = m0 + wm * 64 + mf * 16 + lr;
        #pragma unroll
        for (int nf = 0; nf < 4; nf++) {
            int ncol = n0 + wn * 32 + nf * 8 + 2 * lc;
            *(float2*)&C[(size_t)mrow * N + ncol] =
                make_float2(acc[mf][nf][0], acc[mf][nf][1]);
            *(float2*)&C[(size_t)(mrow + 8) * N + ncol] =
                make_float2(acc[mf][nf][2], acc[mf][nf][3]);
        }
    }
}

// ---------------- rotary + justnorm + sqk scale for q,k --------------------
__global__ void k_rope(float* __restrict__ q, float* __restrict__ k,
                       const float* __restrict__ fc, const float* __restrict__ fs,
                       const float* __restrict__ sqk) {
    int r = blockIdx.x*8 + (threadIdx.x >> 5);  // row over B*S*NH
    int lane = threadIdx.x & 31;
    int h = r & (NH - 1);
    int s = (r >> 4) & (SEQL - 1);
    float c  = fc[s*32 + lane];
    float sn = fs[s*32 + lane];
    float2* qp = (float2*)q + (size_t)r*32 + lane;
    float2* kp = (float2*)k + (size_t)r*32 + lane;
    float2 qv = *qp, kv = *kp;
    float qa = qv.x*c - qv.y*sn, qb = qv.x*sn + qv.y*c;
    float ka = kv.x*c - kv.y*sn, kb = kv.x*sn + kv.y*c;
    float sq = qa*qa + qb*qb, sk = ka*ka + kb*kb;
    #pragma unroll
    for (int o = 16; o > 0; o >>= 1) {
        sq += __shfl_xor_sync(0xffffffffu, sq, o);
        sk += __shfl_xor_sync(0xffffffffu, sk, o);
    }
    float iq = 1.0f / fmaxf(sqrtf(sq), 1e-12f);
    float ik = 1.0f / fmaxf(sqrtf(sk), 1e-12f);
    float s0 = sqk[h*HD + 2*lane    ] * 32.0f;   // sqrt(DIM)=32
    float s1 = sqk[h*HD + 2*lane + 1] * 32.0f;
    *qp = make_float2(qa*iq*s0, qb*iq*s1);
    *kp = make_float2(ka*ik*s0, kb*ik*s1);
}

// ---------------- flash-style attention (no mask) --------------------------
#define APAD 68
#define ATTN_SMEM (4*64*APAD*4)
__global__ __launch_bounds__(256) void k_attn(const float* __restrict__ q,
                                              const float* __restrict__ k,
                                              const float* __restrict__ v,
                                              float* __restrict__ o) {
    extern __shared__ float sm[];
    float* Qs = sm;                    // [64][APAD]
    float* Ks = sm + 64*APAD;
    float* Vs = sm + 2*64*APAD;
    float* Ps = sm + 3*64*APAD;
    int qt = blockIdx.x, h = blockIdx.y, b = blockIdx.z;
    int tid = threadIdx.x;
    for (int i = tid; i < 64*64; i += 256) {
        int r = i >> 6, d = i & 63;
        Qs[r*APAD + d] = q[(((size_t)b*SEQL + qt*64 + r)*NH + h)*HD + d];
    }
    int qrow = tid >> 2, seg = tid & 3;
    float mrow = -1e30f, l = 0.0f;
    float oacc[16];
    #pragma unroll
    for (int i = 0; i < 16; i++) oacc[i] = 0.0f;

    for (int kt = 0; kt < SEQL/64; kt++) {
        __syncthreads();
        for (int i = tid; i < 64*64; i += 256) {
            int r = i >> 6, d = i & 63;
            size_t gi = (((size_t)b*SEQL + kt*64 + r)*NH + h)*HD + d;
            Ks[r*APAD + d] = k[gi];
            Vs[r*APAD + d] = v[gi];
        }
        __syncthreads();
        float s[16];
        #pragma unroll
        for (int j = 0; j < 16; j++) s[j] = 0.0f;
        #pragma unroll 4
        for (int d4 = 0; d4 < 64; d4 += 4) {
            float4 qv = *(float4*)&Qs[qrow*APAD + d4];
            #pragma unroll
            for (int j = 0; j < 16; j++) {
                float4 kv = *(float4*)&Ks[(seg + 4*j)*APAD + d4];
                s[j] += qv.x*kv.x + qv.y*kv.y + qv.z*kv.z + qv.w*kv.w;
            }
        }
        float mx = -1e30f;
        #pragma unroll
        for (int j = 0; j < 16; j++) { s[j] *= 8.0f; mx = fmaxf(mx, s[j]); }
        mx = fmaxf(mx, __shfl_xor_sync(0xffffffffu, mx, 1));
        mx = fmaxf(mx, __shfl_xor_sync(0xffffffffu, mx, 2));
        float mnew = fmaxf(mrow, mx);
        float corr = expf(mrow - mnew);
        float ps = 0.0f;
        #pragma unroll
        for (int j = 0; j < 16; j++) { s[j] = expf(s[j] - mnew); ps += s[j]; }
        ps += __shfl_xor_sync(0xffffffffu, ps, 1);
        ps += __shfl_xor_sync(0xffffffffu, ps, 2);
        l = l*corr + ps;
        mrow = mnew;
        #pragma unroll
        for (int i = 0; i < 16; i++) oacc[i] *= corr;
        #pragma unroll
        for (int j = 0; j < 16; j++) Ps[qrow*APAD + seg + 4*j] = s[j];
        __syncwarp();
        #pragma unroll 2
        for (int kk = 0; kk < 64; kk++) {
            float p = Ps[qrow*APAD + kk];
            const float4* vr = (const float4*)&Vs[kk*APAD + seg*16];
            float4 v0 = vr[0], v1 = vr[1], v2 = vr[2], v3 = vr[3];
            oacc[0]  += p*v0.x; oacc[1]  += p*v0.y; oacc[2]  += p*v0.z; oacc[3]  += p*v0.w;
            oacc[4]  += p*v1.x; oacc[5]  += p*v1.y; oacc[6]  += p*v1.z; oacc[7]  += p*v1.w;
            oacc[8]  += p*v2.x; oacc[9]  += p*v2.y; oacc[10] += p*v2.z; oacc[11] += p*v2.w;
            oacc[12] += p*v3.x; oacc[13] += p*v3.y; oacc[14] += p*v3.z; oacc[15] += p*v3.w;
        }
    }
    float inv = 1.0f / l;
    float* op = &o[(((size_t)b*SEQL + qt*64 + qrow)*NH + h)*HD + seg*16];
    #pragma unroll
    for (int i4 = 0; i4 < 4; i4++)
        ((float4*)op)[i4] = make_float4(oacc[i4*4]*inv, oacc[i4*4+1]*inv,
                                        oacc[i4*4+2]*inv, oacc[i4*4+3]*inv);
}

// ---------------- residual: out = norm(norm(x) + lr*(norm(hn)-norm(x))) ----
__device__ __forceinline__ float blockReduceSum256(float v) {
    __shared__ float red[8];
    #pragma unroll
    for (int o = 16; o > 0; o >>= 1) v += __shfl_xor_sync(0xffffffffu, v, o);
    __syncthreads();
    if ((threadIdx.x & 31) == 0) red[threadIdx.x >> 5] = v;
    __syncthreads();
    return red[0]+red[1]+red[2]+red[3]+red[4]+red[5]+red[6]+red[7];
}

__global__ __launch_bounds__(256) void k_residual(const float* __restrict__ x,
                                                  const float* __restrict__ hn,
                                                  const float* __restrict__ alpha,
                                                  float* __restrict__ out) {
    size_t row = blockIdx.x;
    int tid = threadIdx.x;
    const float* xr = x  + row*DIM;
    const float* ar = hn + row*DIM;
    float xs[4], as[4];
    float ssx = 0.0f, ssa = 0.0f;
    #pragma unroll
    for (int i = 0; i < 4; i++) {
        int c = tid + i*256;
        xs[i] = xr[c]; as[i] = ar[c];
        ssx += xs[i]*xs[i]; ssa += as[i]*as[i];
    }
    ssx = blockReduceSum256(ssx);
    ssa = blockReduceSum256(ssa);
    float ix = 1.0f / fmaxf(sqrtf(ssx), 1e-12f);
    float ia = 1.0f / fmaxf(sqrtf(ssa), 1e-12f);
    float y[4]; float ssy = 0.0f;
    #pragma unroll
    for (int i = 0; i < 4; i++) {
        int c = tid + i*256;
        float lr = fabsf(alpha[c] * 1.6f);   // 0.05*sqrt(1024)
        float hh = xs[i]*ix;
        float aa = as[i]*ia;
        y[i] = hh + lr*(aa - hh);
        ssy += y[i]*y[i];
    }
    ssy = blockReduceSum256(ssy);
    float iy = 1.0f / fmaxf(sqrtf(ssy), 1e-12f);
    #pragma unroll
    for (int i = 0; i < 4; i++) out[row*DIM + tid + i*256] = y[i]*iy;
}

// ---------------- GLU: a = silu(a*sv*sqrt(HID)) * (b3*su), in place --------
__global__ void k_glu(float* __restrict__ a, const float* __restrict__ b3,
                      const float* __restrict__ su, const float* __restrict__ sv) {
    int j = blockIdx.x*256 + threadIdx.x;   // column 0..2815
    size_t i = (size_t)blockIdx.y*HID + j;
    float z = a[i] * sv[j] * sqrtf((float)HID);
    float g = z / (1.0f + expf(-z));
    a[i] = g * (b3[i] * su[j]);
}

// ---------------- launch ---------------------------------------------------
extern "C" void kernel_launch(void* const* d_in, const int* in_sizes, int n_in,
                              void* d_out, int out_size) {
    const float* x   = (const float*)d_in[0];
    const float* fc  = (const float*)d_in[1];
    const float* fs  = (const float*)d_in[2];
    const float* ada = (const float*)d_in[3];
    const float* wq  = (const float*)d_in[4];
    const float* wk  = (const float*)d_in[5];
    const float* wv  = (const float*)d_in[6];
    const float* wo  = (const float*)d_in[7];
    const float* sqk = (const float*)d_in[8];
    const float* w1  = (const float*)d_in[9];
    const float* w2  = (const float*)d_in[10];
    const float* w3  = (const float*)d_in[11];
    const float* su  = (const float*)d_in[12];
    const float* sv  = (const float*)d_in[13];
    const float* pw  = (const float*)d_in[14];
    const float* pb  = (const float*)d_in[15];
    const float* aal = (const float*)d_in[16];
    const float* mal = (const float*)d_in[17];
    float* out = (float*)d_out;

    float *p_mod, *p_q, *p_k, *p_v, *p_ao, *p_x2, *p_b1, *p_b2, *p_t, *p_cv;
    cudaGetSymbolAddress((void**)&p_mod, sc_mod);
    cudaGetSymbolAddress((void**)&p_q,   sc_q);
    cudaGetSymbolAddress((void**)&p_k,   sc_k);
    cudaGetSymbolAddress((void**)&p_v,   sc_v);
    cudaGetSymbolAddress((void**)&p_ao,  sc_ao);
    cudaGetSymbolAddress((void**)&p_x2,  sc_x2);
    cudaGetSymbolAddress((void**)&p_b1,  sc_b1);
    cudaGetSymbolAddress((void**)&p_b2,  sc_b2);
    cudaGetSymbolAddress((void**)&p_t,   sc_t);
    cudaGetSymbolAddress((void**)&p_cv,  sc_cv);

    cudaFuncSetAttribute(k_attn, cudaFuncAttributeMaxDynamicSharedMemorySize, ATTN_SMEM);
    cudaFuncSetAttribute(k_gemm_tf32, cudaFuncAttributeMaxDynamicSharedMemorySize, GEMM_SMEM);

    // time modulation coefficients -> circular conv kernels
    k_timeproj<<<2, 512>>>(ada, pw, pb, p_t);
    k_makeconv<<<4, 256>>>(p_t, p_cv);

    // ---- attention branch ----
    k_modulate<<<dim3(8192, BB), 256>>>(x, p_cv, 0, p_mod);
    dim3 gQ(DIM/128, BS/128);
    k_gemm_tf32<<<gQ, 256, GEMM_SMEM>>>(p_mod, wq, p_q, BS, DIM, DIM);
    k_gemm_tf32<<<gQ, 256, GEMM_SMEM>>>(p_mod, wk, p_k, BS, DIM, DIM);
    k_gemm_tf32<<<gQ, 256, GEMM_SMEM>>>(p_mod, wv, p_v, BS, DIM, DIM);
    k_rope<<<(BS*NH)/8, 256>>>(p_q, p_k, fc, fs, sqk);
    k_attn<<<dim3(SEQL/64, NH, BB), 256, ATTN_SMEM>>>(p_q, p_k, p_v, p_ao);
    k_gemm_tf32<<<gQ, 256, GEMM_SMEM>>>(p_ao, wo, p_mod, BS, DIM, DIM);   // h_a
    k_residual<<<BS, 256>>>(x, p_mod, aal, p_x2);

    // ---- mlp branch ----
    k_modulate<<<dim3(8192, BB), 256>>>(p_x2, p_cv, 1, p_q);  // reuse p_q
    dim3 gF(HID/128, BS/128);
    k_gemm_tf32<<<gF, 256, GEMM_SMEM>>>(p_q, w1, p_b1, BS, HID, DIM);
    k_gemm_tf32<<<gF, 256, GEMM_SMEM>>>(p_q, w3, p_b2, BS, HID, DIM);
    k_glu<<<dim3(HID/256, BS), 256>>>(p_b1, p_b2, su, sv);
    k_gemm_tf32<<<dim3(DIM/128, BS/128), 256, GEMM_SMEM>>>(p_b1, w2, p_k, BS, DIM, HID);
    k_residual<<<BS, 256>>>(p_x2, p_k, mal, out);
}

// round 11
// speedup vs baseline: 2.9921x; 2.4591x over previous
#include <cuda_runtime.h>
#include <math.h>
#include <stdint.h>

#define BB   2
#define SEQL 2048
#define DIM  1024
#define NH   16
#define HD   64
#define HID  2816
#define BS   (BB*SEQL)   // 4096

// ---------------- scratch (static device memory; no allocation allowed) ----
__device__ float sc_mod[(size_t)BS*DIM];
__device__ float sc_q  [(size_t)BS*DIM];
__device__ float sc_k  [(size_t)BS*DIM];
__device__ float sc_v  [(size_t)BS*DIM];
__device__ float sc_ao [(size_t)BS*DIM];
__device__ float sc_x2 [(size_t)BS*DIM];
__device__ float sc_b1 [(size_t)BS*HID];
__device__ float sc_b2 [(size_t)BS*HID];
__device__ float sc_t  [BB*512];
__device__ float sc_cv [BB*2*256];

// ---------------- async-copy helpers --------------------------------------
__device__ __forceinline__ void cpa16(float* s, const float* g) {
    uint32_t sa = (uint32_t)__cvta_generic_to_shared(s);
    asm volatile("cp.async.cg.shared.global [%0], [%1], 16;" :: "r"(sa), "l"(g));
}
#define CP_COMMIT() asm volatile("cp.async.commit_group;")
#define CP_WAIT1()  asm volatile("cp.async.wait_group 1;")

__device__ __forceinline__ void mma_tf32(float* d, const uint32_t* a, const uint32_t* b) {
    asm volatile("mma.sync.aligned.m16n8k8.row.col.f32.tf32.tf32.f32 "
        "{%0,%1,%2,%3}, {%4,%5,%6,%7}, {%8,%9}, {%0,%1,%2,%3};\n"
        : "+f"(d[0]), "+f"(d[1]), "+f"(d[2]), "+f"(d[3])
        : "r"(a[0]), "r"(a[1]), "r"(a[2]), "r"(a[3]), "r"(b[0]), "r"(b[1]));
}

// ---------------- time projection: t = silu(ada) @ proj_w + proj_b --------
__global__ void k_timeproj(const float* __restrict__ ada, const float* __restrict__ pw,
                           const float* __restrict__ pb, float* __restrict__ t) {
    __shared__ float sa[DIM];
    int b = blockIdx.x;
    int j = threadIdx.x;              // 512 threads
    for (int i = j; i < DIM; i += 512) {
        float v = ada[b*DIM + i];
        sa[i] = v / (1.0f + expf(-v));
    }
    __syncthreads();
    float acc = pb[j];
    #pragma unroll 8
    for (int k = 0; k < DIM; k++) acc += sa[k] * pw[k*512 + j];
    t[b*512 + j] = acc;
}

// ------ build circular-conv kernel: g[n] = (1/256) sum_k f[k] cos(2pi k n/256)
__global__ void k_makeconv(const float* __restrict__ t, float* __restrict__ cv) {
    int slot = blockIdx.x;            // b*2 + which
    int b = slot >> 1, w = slot & 1;
    int n = threadIdx.x;              // 256
    const float* f = t + b*512 + w*256;
    float acc = 0.0f;
    #pragma unroll 4
    for (int k = 0; k < 256; k++) {
        int kn = (k * n) & 255;
        acc += f[k] * cospif(kn * (2.0f / 256.0f));
    }
    cv[slot*256 + n] = acc * (1.0f / 256.0f);
}

// ------ adafm_modulate == per-16x16-patch circular conv (len 256) ----------
__global__ __launch_bounds__(256) void k_modulate(const float* __restrict__ x,
                                                  const float* __restrict__ cv, int which,
                                                  float* __restrict__ out) {
    int b = blockIdx.y;
    int patch = blockIdx.x;           // 0..8191
    int ir = patch >> 6, ic = patch & 63;
    int m = threadIdx.x;              // 0..255
    __shared__ float xp[256], gs[256];
    gs[m] = cv[(b*2 + which)*256 + m];
    int pr = m >> 4, pc = m & 15;
    size_t gi = ((size_t)b*SEQL + ir*16 + pr)*DIM + ic*16 + pc;
    xp[m] = x[gi];
    __syncthreads();
    float acc = 0.0f;
    #pragma unroll 8
    for (int mp = 0; mp < 256; mp++)
        acc += xp[mp] * gs[(m - mp) & 255];
    out[gi] = acc;
}

// ---------------- tf32 tensor-core GEMM, cp.async 3-stage pipeline ---------
// C[M,N] = A[M,K] @ B[K,N] row-major. 128x128 tile, K-step 32, 8 warps (2x4).
// A stage: [m=128][k=32] stride 36 (banks 4m+k distinct per frag load).
// B stage: [k=32][n=128] stride 136 (banks 8k+n distinct per frag load).
#define GA_STR 36
#define GB_STR 136
#define G_ASTG (128*GA_STR)          // 4608 floats
#define G_BSTG (32*GB_STR)           // 4352 floats
#define G_STG  (G_ASTG + G_BSTG)     // 8960 floats
#define GEMM_SMEM (3*G_STG*4)        // 107520 bytes

__global__ __launch_bounds__(256,2) void k_gemm_tf32(const float* __restrict__ A,
                                                     const float* __restrict__ B,
                                                     float* __restrict__ C,
                                                     int M, int N, int K) {
    extern __shared__ float smg[];
    const int tid  = threadIdx.x;
    const int lane = tid & 31, wid = tid >> 5;
    const int wm = wid >> 2, wn = wid & 3;
    const int m0 = blockIdx.y * 128, n0 = blockIdx.x * 128;
    const int lr = lane >> 2, lc = lane & 3;

    float acc[4][4][4];
    #pragma unroll
    for (int i = 0; i < 4; i++)
        #pragma unroll
        for (int j = 0; j < 4; j++)
            #pragma unroll
            for (int r = 0; r < 4; r++) acc[i][j][r] = 0.0f;

    const int a_m = tid >> 1, a_k = (tid & 1) * 16;
    const int b_k = tid >> 3, b_n = (tid & 7) * 16;
    const float* Ag = A + (size_t)(m0 + a_m) * K + a_k;
    const float* Bg = B + (size_t)b_k * N + n0 + b_n;

    const int KT = K >> 5;

    // prologue: stages 0,1
    #pragma unroll
    for (int p = 0; p < 2; p++) {
        float* As = smg + p * G_STG;
        float* Bs = As + G_ASTG;
        const float* ap = Ag + p * 32;
        const float* bp = Bg + (size_t)p * 32 * N;
        #pragma unroll
        for (int i = 0; i < 4; i++) cpa16(As + a_m*GA_STR + a_k + 4*i, ap + 4*i);
        #pragma unroll
        for (int i = 0; i < 4; i++) cpa16(Bs + b_k*GB_STR + b_n + 4*i, bp + 4*i);
        CP_COMMIT();
    }

    for (int kt = 0; kt < KT; kt++) {
        CP_WAIT1();
        __syncthreads();
        if (kt + 2 < KT) {
            int slot = (kt + 2) % 3;
            float* As = smg + slot * G_STG;
            float* Bs = As + G_ASTG;
            const float* ap = Ag + (kt + 2) * 32;
            const float* bp = Bg + (size_t)(kt + 2) * 32 * N;
            #pragma unroll
            for (int i = 0; i < 4; i++) cpa16(As + a_m*GA_STR + a_k + 4*i, ap + 4*i);
            #pragma unroll
            for (int i = 0; i < 4; i++) cpa16(Bs + b_k*GB_STR + b_n + 4*i, bp + 4*i);
        }
        CP_COMMIT();

        const uint32_t* As = (const uint32_t*)(smg + (kt % 3) * G_STG);
        const uint32_t* Bs = As + G_ASTG;
        #pragma unroll
        for (int ks = 0; ks < 4; ks++) {
            const int k = ks * 8 + lc;
            uint32_t af[4][4], bf[4][2];
            #pragma unroll
            for (int mf = 0; mf < 4; mf++) {
                int m = wm * 64 + mf * 16 + lr;
                af[mf][0] = As[(m    )*GA_STR + k];
                af[mf][1] = As[(m + 8)*GA_STR + k];
                af[mf][2] = As[(m    )*GA_STR + k + 4];
                af[mf][3] = As[(m + 8)*GA_STR + k + 4];
            }
            #pragma unroll
            for (int nf = 0; nf < 4; nf++) {
                int n = wn * 32 + nf * 8 + lr;
                bf[nf][0] = Bs[(k    )*GB_STR + n];
                bf[nf][1] = Bs[(k + 4)*GB_STR + n];
            }
            #pragma unroll
            for (int mf = 0; mf < 4; mf++)
                #pragma unroll
                for (int nf = 0; nf < 4; nf++)
                    mma_tf32(acc[mf][nf], af[mf], bf[nf]);
        }
    }

    #pragma unroll
    for (int mf = 0; mf < 4; mf++) {
        int mrow = m0 + wm * 64 + mf * 16 + lr;
        #pragma unroll
        for (int nf = 0; nf < 4; nf++) {
            int ncol = n0 + wn * 32 + nf * 8 + 2 * lc;
            *(float2*)&C[(size_t)mrow * N + ncol] =
                make_float2(acc[mf][nf][0], acc[mf][nf][1]);
            *(float2*)&C[(size_t)(mrow + 8) * N + ncol] =
                make_float2(acc[mf][nf][2], acc[mf][nf][3]);
        }
    }
}

// ---------------- rotary + justnorm + sqk scale for q,k --------------------
__global__ void k_rope(float* __restrict__ q, float* __restrict__ k,
                       const float* __restrict__ fc, const float* __restrict__ fs,
                       const float* __restrict__ sqk) {
    int r = blockIdx.x*8 + (threadIdx.x >> 5);  // row over B*S*NH
    int lane = threadIdx.x & 31;
    int h = r & (NH - 1);
    int s = (r >> 4) & (SEQL - 1);
    float c  = fc[s*32 + lane];
    float sn = fs[s*32 + lane];
    float2* qp = (float2*)q + (size_t)r*32 + lane;
    float2* kp = (float2*)k + (size_t)r*32 + lane;
    float2 qv = *qp, kv = *kp;
    float qa = qv.x*c - qv.y*sn, qb = qv.x*sn + qv.y*c;
    float ka = kv.x*c - kv.y*sn, kb = kv.x*sn + kv.y*c;
    float sq = qa*qa + qb*qb, sk = ka*ka + kb*kb;
    #pragma unroll
    for (int o = 16; o > 0; o >>= 1) {
        sq += __shfl_xor_sync(0xffffffffu, sq, o);
        sk += __shfl_xor_sync(0xffffffffu, sk, o);
    }
    float iq = 1.0f / fmaxf(sqrtf(sq), 1e-12f);
    float ik = 1.0f / fmaxf(sqrtf(sk), 1e-12f);
    float s0 = sqk[h*HD + 2*lane    ] * 32.0f;   // sqrt(DIM)=32
    float s1 = sqk[h*HD + 2*lane + 1] * 32.0f;
    *qp = make_float2(qa*iq*s0, qb*iq*s1);
    *kp = make_float2(ka*ik*s0, kb*ik*s1);
}

// ---------------- tensor-core flash attention (no mask) --------------------
// Block: 128 q-rows x 1 head. 8 warps; warp w owns q rows w*16..w*16+15, all keys.
// Qs: K-major [d=64][m=128] stride 136; Ps same. Ks/Vs natural [krow=64][d=64]
// stride 76, cp.async double-buffered.
#define QSTR   136
#define KVSTR  76
#define KBUF   (64*KVSTR)            // 4864 floats
#define AQ_OFF 0
#define AK_OFF (64*QSTR)             // 8704
#define AV_OFF (AK_OFF + 2*KBUF)     // 18432
#define AP_OFF (AV_OFF + 2*KBUF)     // 28160
#define ATTN_SMEM ((AP_OFF + 64*QSTR)*4)   // 147456 bytes

__global__ __launch_bounds__(256) void k_attn_tc(const float* __restrict__ qg,
                                                 const float* __restrict__ kg,
                                                 const float* __restrict__ vg,
                                                 float* __restrict__ og) {
    extern __shared__ float sm[];
    const int tid  = threadIdx.x;
    const int lane = tid & 31, wid = tid >> 5;
    const int lr = lane >> 2, lc = lane & 3;
    const int qt = blockIdx.x, h = blockIdx.y, b = blockIdx.z;
    const size_t hoff = (size_t)b * SEQL * DIM + h * HD;
    const int mrow = wid * 16 + lr;

    // ---- load Q tile (transpose to K-major) ----
    {
        int qrow = tid >> 1, db = (tid & 1) * 32;
        const float* qp = qg + hoff + (size_t)(qt*128 + qrow) * DIM + db;
        #pragma unroll
        for (int j = 0; j < 8; j++) {
            float4 qv = *(const float4*)(qp + 4*j);
            int d = db + 4*j;
            sm[(d+0)*QSTR + qrow] = qv.x;
            sm[(d+1)*QSTR + qrow] = qv.y;
            sm[(d+2)*QSTR + qrow] = qv.z;
            sm[(d+3)*QSTR + qrow] = qv.w;
        }
    }

    const int krow = tid >> 2, dsel = (tid & 3) * 4;

    // prologue: tile 0
    {
        const float* kp = kg + hoff + (size_t)krow * DIM + dsel;
        const float* vp = vg + hoff + (size_t)krow * DIM + dsel;
        float* kd = sm + AK_OFF + krow*KVSTR + dsel;
        float* vd = sm + AV_OFF + krow*KVSTR + dsel;
        #pragma unroll
        for (int j = 0; j < 4; j++) { cpa16(kd + 16*j, kp + 16*j); cpa16(vd + 16*j, vp + 16*j); }
        CP_COMMIT();
    }

    float mr0 = -1e30f, mr1 = -1e30f, l0 = 0.0f, l1 = 0.0f;
    float oa[8][4];
    #pragma unroll
    for (int nf = 0; nf < 8; nf++)
        #pragma unroll
        for (int r = 0; r < 4; r++) oa[nf][r] = 0.0f;

    const uint32_t* Qsu = (const uint32_t*)(sm + AQ_OFF);
    const uint32_t* Psu = (const uint32_t*)(sm + AP_OFF);
    float* Ps = sm + AP_OFF;

    for (int kt = 0; kt < SEQL/64; kt++) {
        if (kt) __syncthreads();   // all readers of buffer (kt+1)&1 (tile kt-1) done
        if (kt + 1 < SEQL/64) {
            int buf = (kt + 1) & 1;
            const float* kp = kg + hoff + (size_t)((kt+1)*64 + krow) * DIM + dsel;
            const float* vp = vg + hoff + (size_t)((kt+1)*64 + krow) * DIM + dsel;
            float* kd = sm + AK_OFF + buf*KBUF + krow*KVSTR + dsel;
            float* vd = sm + AV_OFF + buf*KBUF + krow*KVSTR + dsel;
            #pragma unroll
            for (int j = 0; j < 4; j++) { cpa16(kd + 16*j, kp + 16*j); cpa16(vd + 16*j, vp + 16*j); }
        }
        CP_COMMIT();
        CP_WAIT1();
        __syncthreads();

        const uint32_t* Ksu = (const uint32_t*)(sm + AK_OFF + (kt & 1)*KBUF);
        const uint32_t* Vsu = (const uint32_t*)(sm + AV_OFF + (kt & 1)*KBUF);

        // ---- S = Q @ K^T ----
        float s_[8][4];
        #pragma unroll
        for (int nf = 0; nf < 8; nf++)
            #pragma unroll
            for (int r = 0; r < 4; r++) s_[nf][r] = 0.0f;
        #pragma unroll
        for (int ks = 0; ks < 8; ks++) {
            const int k8 = ks * 8 + lc;
            uint32_t a[4];
            a[0] = Qsu[(k8    )*QSTR + mrow];
            a[1] = Qsu[(k8    )*QSTR + mrow + 8];
            a[2] = Qsu[(k8 + 4)*QSTR + mrow];
            a[3] = Qsu[(k8 + 4)*QSTR + mrow + 8];
            #pragma unroll
            for (int nf = 0; nf < 8; nf++) {
                const int n = nf * 8 + lr;
                uint32_t bfr[2];
                bfr[0] = Ksu[n*KVSTR + k8];
                bfr[1] = Ksu[n*KVSTR + k8 + 4];
                mma_tf32(s_[nf], a, bfr);
            }
        }

        // ---- online softmax (rows lr and lr+8, cols covered by 4-lane group) ----
        float mx0 = -1e30f, mx1 = -1e30f;
        #pragma unroll
        for (int nf = 0; nf < 8; nf++) {
            s_[nf][0] *= 8.0f; s_[nf][1] *= 8.0f; s_[nf][2] *= 8.0f; s_[nf][3] *= 8.0f;
            mx0 = fmaxf(mx0, fmaxf(s_[nf][0], s_[nf][1]));
            mx1 = fmaxf(mx1, fmaxf(s_[nf][2], s_[nf][3]));
        }
        mx0 = fmaxf(mx0, __shfl_xor_sync(0xffffffffu, mx0, 1));
        mx0 = fmaxf(mx0, __shfl_xor_sync(0xffffffffu, mx0, 2));
        mx1 = fmaxf(mx1, __shfl_xor_sync(0xffffffffu, mx1, 1));
        mx1 = fmaxf(mx1, __shfl_xor_sync(0xffffffffu, mx1, 2));
        float mn0 = fmaxf(mr0, mx0), mn1 = fmaxf(mr1, mx1);
        float cr0 = __expf(mr0 - mn0), cr1 = __expf(mr1 - mn1);
        float ps0 = 0.0f, ps1 = 0.0f;
        #pragma unroll
        for (int nf = 0; nf < 8; nf++) {
            s_[nf][0] = __expf(s_[nf][0] - mn0);
            s_[nf][1] = __expf(s_[nf][1] - mn0);
            s_[nf][2] = __expf(s_[nf][2] - mn1);
            s_[nf][3] = __expf(s_[nf][3] - mn1);
            ps0 += s_[nf][0] + s_[nf][1];
            ps1 += s_[nf][2] + s_[nf][3];
        }
        ps0 += __shfl_xor_sync(0xffffffffu, ps0, 1);
        ps0 += __shfl_xor_sync(0xffffffffu, ps0, 2);
        ps1 += __shfl_xor_sync(0xffffffffu, ps1, 1);
        ps1 += __shfl_xor_sync(0xffffffffu, ps1, 2);
        l0 = l0 * cr0 + ps0;
        l1 = l1 * cr1 + ps1;
        mr0 = mn0; mr1 = mn1;
        #pragma unroll
        for (int nf = 0; nf < 8; nf++) {
            oa[nf][0] *= cr0; oa[nf][1] *= cr0;
            oa[nf][2] *= cr1; oa[nf][3] *= cr1;
        }

        // ---- write P (warp-private m-columns, K-major) ----
        __syncwarp();
        #pragma unroll
        for (int nf = 0; nf < 8; nf++) {
            int n = nf * 8 + 2 * lc;
            Ps[(n    )*QSTR + mrow    ] = s_[nf][0];
            Ps[(n + 1)*QSTR + mrow    ] = s_[nf][1];
            Ps[(n    )*QSTR + mrow + 8] = s_[nf][2];
            Ps[(n + 1)*QSTR + mrow + 8] = s_[nf][3];
        }
        __syncwarp();

        // ---- O += P @ V ----
        #pragma unroll
        for (int ks = 0; ks < 8; ks++) {
            const int k8 = ks * 8 + lc;
            uint32_t a[4];
            a[0] = Psu[(k8    )*QSTR + mrow];
            a[1] = Psu[(k8    )*QSTR + mrow + 8];
            a[2] = Psu[(k8 + 4)*QSTR + mrow];
            a[3] = Psu[(k8 + 4)*QSTR + mrow + 8];
            #pragma unroll
            for (int nf = 0; nf < 8; nf++) {
                const int n = nf * 8 + lr;
                uint32_t bfr[2];
                bfr[0] = Vsu[(k8    )*KVSTR + n];
                bfr[1] = Vsu[(k8 + 4)*KVSTR + n];
                mma_tf32(oa[nf], a, bfr);
            }
        }
    }

    // ---- epilogue ----
    float i0 = 1.0f / l0, i1 = 1.0f / l1;
    float* or0 = og + hoff + (size_t)(qt*128 + mrow) * DIM;
    float* or1 = or0 + 8 * DIM;
    #pragma unroll
    for (int nf = 0; nf < 8; nf++) {
        int d = nf * 8 + 2 * lc;
        *(float2*)&or0[d] = make_float2(oa[nf][0]*i0, oa[nf][1]*i0);
        *(float2*)&or1[d] = make_float2(oa[nf][2]*i1, oa[nf][3]*i1);
    }
}

// ---------------- residual: out = norm(norm(x) + lr*(norm(hn)-norm(x))) ----
__device__ __forceinline__ float blockReduceSum256(float v) {
    __shared__ float red[8];
    #pragma unroll
    for (int o = 16; o > 0; o >>= 1) v += __shfl_xor_sync(0xffffffffu, v, o);
    __syncthreads();
    if ((threadIdx.x & 31) == 0) red[threadIdx.x >> 5] = v;
    __syncthreads();
    return red[0]+red[1]+red[2]+red[3]+red[4]+red[5]+red[6]+red[7];
}

__global__ __launch_bounds__(256) void k_residual(const float* __restrict__ x,
                                                  const float* __restrict__ hn,
                                                  const float* __restrict__ alpha,
                                                  float* __restrict__ out) {
    size_t row = blockIdx.x;
    int tid = threadIdx.x;
    const float* xr = x  + row*DIM;
    const float* ar = hn + row*DIM;
    float xs[4], as[4];
    float ssx = 0.0f, ssa = 0.0f;
    #pragma unroll
    for (int i = 0; i < 4; i++) {
        int c = tid + i*256;
        xs[i] = xr[c]; as[i] = ar[c];
        ssx += xs[i]*xs[i]; ssa += as[i]*as[i];
    }
    ssx = blockReduceSum256(ssx);
    ssa = blockReduceSum256(ssa);
    float ix = 1.0f / fmaxf(sqrtf(ssx), 1e-12f);
    float ia = 1.0f / fmaxf(sqrtf(ssa), 1e-12f);
    float y[4]; float ssy = 0.0f;
    #pragma unroll
    for (int i = 0; i < 4; i++) {
        int c = tid + i*256;
        float lr = fabsf(alpha[c] * 1.6f);   // 0.05*sqrt(1024)
        float hh = xs[i]*ix;
        float aa = as[i]*ia;
        y[i] = hh + lr*(aa - hh);
        ssy += y[i]*y[i];
    }
    ssy = blockReduceSum256(ssy);
    float iy = 1.0f / fmaxf(sqrtf(ssy), 1e-12f);
    #pragma unroll
    for (int i = 0; i < 4; i++) out[row*DIM + tid + i*256] = y[i]*iy;
}

// ---------------- GLU: a = silu(a*sv*sqrt(HID)) * (b3*su), in place --------
__global__ void k_glu(float* __restrict__ a, const float* __restrict__ b3,
                      const float* __restrict__ su, const float* __restrict__ sv) {
    int j = blockIdx.x*256 + threadIdx.x;   // column 0..2815
    size_t i = (size_t)blockIdx.y*HID + j;
    float z = a[i] * sv[j] * sqrtf((float)HID);
    float g = z / (1.0f + expf(-z));
    a[i] = g * (b3[i] * su[j]);
}

// ---------------- launch ---------------------------------------------------
extern "C" void kernel_launch(void* const* d_in, const int* in_sizes, int n_in,
                              void* d_out, int out_size) {
    const float* x   = (const float*)d_in[0];
    const float* fc  = (const float*)d_in[1];
    const float* fs  = (const float*)d_in[2];
    const float* ada = (const float*)d_in[3];
    const float* wq  = (const float*)d_in[4];
    const float* wk  = (const float*)d_in[5];
    const float* wv  = (const float*)d_in[6];
    const float* wo  = (const float*)d_in[7];
    const float* sqk = (const float*)d_in[8];
    const float* w1  = (const float*)d_in[9];
    const float* w2  = (const float*)d_in[10];
    const float* w3  = (const float*)d_in[11];
    const float* su  = (const float*)d_in[12];
    const float* sv  = (const float*)d_in[13];
    const float* pw  = (const float*)d_in[14];
    const float* pb  = (const float*)d_in[15];
    const float* aal = (const float*)d_in[16];
    const float* mal = (const float*)d_in[17];
    float* out = (float*)d_out;

    float *p_mod, *p_q, *p_k, *p_v, *p_ao, *p_x2, *p_b1, *p_b2, *p_t, *p_cv;
    cudaGetSymbolAddress((void**)&p_mod, sc_mod);
    cudaGetSymbolAddress((void**)&p_q,   sc_q);
    cudaGetSymbolAddress((void**)&p_k,   sc_k);
    cudaGetSymbolAddress((void**)&p_v,   sc_v);
    cudaGetSymbolAddress((void**)&p_ao,  sc_ao);
    cudaGetSymbolAddress((void**)&p_x2,  sc_x2);
    cudaGetSymbolAddress((void**)&p_b1,  sc_b1);
    cudaGetSymbolAddress((void**)&p_b2,  sc_b2);
    cudaGetSymbolAddress((void**)&p_t,   sc_t);
    cudaGetSymbolAddress((void**)&p_cv,  sc_cv);

    cudaFuncSetAttribute(k_attn_tc, cudaFuncAttributeMaxDynamicSharedMemorySize, ATTN_SMEM);
    cudaFuncSetAttribute(k_gemm_tf32, cudaFuncAttributeMaxDynamicSharedMemorySize, GEMM_SMEM);

    // time modulation coefficients -> circular conv kernels
    k_timeproj<<<2, 512>>>(ada, pw, pb, p_t);
    k_makeconv<<<4, 256>>>(p_t, p_cv);

    // ---- attention branch ----
    k_modulate<<<dim3(8192, BB), 256>>>(x, p_cv, 0, p_mod);
    dim3 gQ(DIM/128, BS/128);
    k_gemm_tf32<<<gQ, 256, GEMM_SMEM>>>(p_mod, wq, p_q, BS, DIM, DIM);
    k_gemm_tf32<<<gQ, 256, GEMM_SMEM>>>(p_mod, wk, p_k, BS, DIM, DIM);
    k_gemm_tf32<<<gQ, 256, GEMM_SMEM>>>(p_mod, wv, p_v, BS, DIM, DIM);
    k_rope<<<(BS*NH)/8, 256>>>(p_q, p_k, fc, fs, sqk);
    k_attn_tc<<<dim3(SEQL/128, NH, BB), 256, ATTN_SMEM>>>(p_q, p_k, p_v, p_ao);
    k_gemm_tf32<<<gQ, 256, GEMM_SMEM>>>(p_ao, wo, p_mod, BS, DIM, DIM);   // h_a
    k_residual<<<BS, 256>>>(x, p_mod, aal, p_x2);

    // ---- mlp branch ----
    k_modulate<<<dim3(8192, BB), 256>>>(p_x2, p_cv, 1, p_q);  // reuse p_q
    dim3 gF(HID/128, BS/128);
    k_gemm_tf32<<<gF, 256, GEMM_SMEM>>>(p_q, w1, p_b1, BS, HID, DIM);
    k_gemm_tf32<<<gF, 256, GEMM_SMEM>>>(p_q, w3, p_b2, BS, HID, DIM);
    k_glu<<<dim3(HID/256, BS), 256>>>(p_b1, p_b2, su, sv);
    k_gemm_tf32<<<dim3(DIM/128, BS/128), 256, GEMM_SMEM>>>(p_b1, w2, p_k, BS, DIM, HID);
    k_residual<<<BS, 256>>>(p_x2, p_k, mal, out);
}